// round 2
// baseline (speedup 1.0000x reference)
#include <cuda_runtime.h>
#include <cstdint>

// Problem constants
#define B_  4
#define T_  2048
#define C_  1024
#define H_  16
#define D_  64
#define C3_ 3072

// Scratch (allocation-free rule: __device__ globals)
__device__ float g_qkv[(size_t)B_ * T_ * C3_];   // [B,T,3C]  ~100.7 MB
__device__ float g_att[(size_t)B_ * T_ * C_];    // [B,T,C]   ~33.6 MB

// ---------------------------------------------------------------------------
// Generic SGEMM with bias: C[M,N] = A[M,K] @ B[K,N] + bias[N]
// 64x64 tile, BK=16, 256 threads, 4x4 register tile per thread.
// M % 64 == 0, N % 64 == 0, K % 16 == 0 (true for all our shapes).
// ---------------------------------------------------------------------------
__global__ __launch_bounds__(256) void sgemm_bias(
    const float* __restrict__ A, const float* __restrict__ Bm,
    const float* __restrict__ bias, float* __restrict__ Cm,
    int M, int N, int K)
{
    __shared__ float As[16][64];   // transposed: As[k][m]
    __shared__ float Bs[16][64];   // natural:    Bs[k][n]

    const int tid = threadIdx.x;
    const int ty  = tid >> 4;        // 0..15 -> m sub-tile
    const int tx  = tid & 15;        // 0..15 -> n sub-tile
    const int m0  = blockIdx.y * 64;
    const int n0  = blockIdx.x * 64;

    // load index precompute
    const int am = tid >> 2;         // 0..63
    const int ak = (tid & 3) * 4;    // 0,4,8,12
    const int bk = tid >> 4;         // 0..15
    const int bn = (tid & 15) * 4;   // 0..60

    float acc[4][4] = {};

    for (int k0 = 0; k0 < K; k0 += 16) {
        float4 a = *(const float4*)(A + (size_t)(m0 + am) * K + (k0 + ak));
        As[ak + 0][am] = a.x;
        As[ak + 1][am] = a.y;
        As[ak + 2][am] = a.z;
        As[ak + 3][am] = a.w;
        *(float4*)&Bs[bk][bn] =
            *(const float4*)(Bm + (size_t)(k0 + bk) * N + (n0 + bn));
        __syncthreads();

#pragma unroll
        for (int kk = 0; kk < 16; kk++) {
            float4 a4 = *(float4*)&As[kk][ty * 4];
            float4 b4 = *(float4*)&Bs[kk][tx * 4];
            float ar[4] = {a4.x, a4.y, a4.z, a4.w};
            float br[4] = {b4.x, b4.y, b4.z, b4.w};
#pragma unroll
            for (int i = 0; i < 4; i++)
#pragma unroll
                for (int j = 0; j < 4; j++)
                    acc[i][j] += ar[i] * br[j];
        }
        __syncthreads();
    }

    float4 bb = *(const float4*)(bias + n0 + tx * 4);
    float brr[4] = {bb.x, bb.y, bb.z, bb.w};
#pragma unroll
    for (int i = 0; i < 4; i++) {
        float4 o;
        o.x = acc[i][0] + brr[0];
        o.y = acc[i][1] + brr[1];
        o.z = acc[i][2] + brr[2];
        o.w = acc[i][3] + brr[3];
        *(float4*)(Cm + (size_t)(m0 + ty * 4 + i) * N + (n0 + tx * 4)) = o;
    }
}

// ---------------------------------------------------------------------------
// Causal flash attention, fp32, one CTA per (qtile=64 rows, head, batch).
// qkv layout: [B, T, 3C] with q at col [h*64, +64), k at C + h*64, v at 2C + h*64.
// Online softmax with row state replicated across the 16-thread row group;
// row reductions via width-16 XOR shuffles (row groups are lane-aligned).
// ---------------------------------------------------------------------------
__global__ __launch_bounds__(256) void flash_attn(
    const float* __restrict__ qkv, float* __restrict__ out)
{
    const int qt = blockIdx.x;   // 0..31 (q tile)
    const int h  = blockIdx.y;   // 0..15
    const int b  = blockIdx.z;   // 0..3

    extern __shared__ float sm[];
    float* Qt = sm;               // [64][64]  (d, r) transposed, pre-scaled
    float* Kt = Qt + 64 * 64;     // [64][64]  (d, c) transposed
    float* Vs = Kt + 64 * 64;     // [64][64]  (c, d) natural
    float* Ps = Vs + 64 * 64;     // [64][64]  (r, c) natural

    const int tid = threadIdx.x;
    const int ty  = tid >> 4;     // row group  -> rows r0..r0+3
    const int tx  = tid & 15;     // col group  -> cols c0..c0+3 (also d cols for O)
    const int r0  = ty * 4;
    const int c0  = tx * 4;

    const float scale = 0.125f;   // 1/sqrt(64)

    // Load Q tile transposed, pre-scaled.
    {
        const float* qbase = qkv + ((size_t)(b * T_ + qt * 64) * C3_) + h * 64;
#pragma unroll
        for (int it = 0; it < 4; it++) {
            int i  = tid + it * 256;          // 0..1023
            int r  = i >> 4;
            int d4 = (i & 15) * 4;
            float4 v = *(const float4*)(qbase + (size_t)r * C3_ + d4);
            Qt[(d4 + 0) * 64 + r] = v.x * scale;
            Qt[(d4 + 1) * 64 + r] = v.y * scale;
            Qt[(d4 + 2) * 64 + r] = v.z * scale;
            Qt[(d4 + 3) * 64 + r] = v.w * scale;
        }
    }

    float m_i[4], l_i[4], acc[4][4];
#pragma unroll
    for (int i = 0; i < 4; i++) {
        m_i[i] = -1e30f;
        l_i[i] = 0.0f;
#pragma unroll
        for (int j = 0; j < 4; j++) acc[i][j] = 0.0f;
    }

    for (int kt = 0; kt <= qt; kt++) {
        __syncthreads();  // previous iter's Ps/Vs reads done; Qt visible on iter 0

        // Load K (transposed) and V (natural) tiles.
        {
            const float* kbase = qkv + ((size_t)(b * T_ + kt * 64) * C3_) + C_ + h * 64;
            const float* vbase = kbase + C_;
#pragma unroll
            for (int it = 0; it < 4; it++) {
                int i  = tid + it * 256;
                int c  = i >> 4;
                int d4 = (i & 15) * 4;
                float4 kv = *(const float4*)(kbase + (size_t)c * C3_ + d4);
                Kt[(d4 + 0) * 64 + c] = kv.x;
                Kt[(d4 + 1) * 64 + c] = kv.y;
                Kt[(d4 + 2) * 64 + c] = kv.z;
                Kt[(d4 + 3) * 64 + c] = kv.w;
                *(float4*)(Vs + c * 64 + d4) =
                    *(const float4*)(vbase + (size_t)c * C3_ + d4);
            }
        }
        __syncthreads();

        // S = (Q*scale) K^T
        float s[4][4] = {};
#pragma unroll 16
        for (int d = 0; d < 64; d++) {
            float4 q4 = *(float4*)(Qt + d * 64 + r0);
            float4 k4 = *(float4*)(Kt + d * 64 + c0);
            float qr[4] = {q4.x, q4.y, q4.z, q4.w};
            float kr[4] = {k4.x, k4.y, k4.z, k4.w};
#pragma unroll
            for (int i = 0; i < 4; i++)
#pragma unroll
                for (int j = 0; j < 4; j++)
                    s[i][j] += qr[i] * kr[j];
        }

        // Causal mask (only the diagonal tile needs it).
        if (kt == qt) {
#pragma unroll
            for (int i = 0; i < 4; i++)
#pragma unroll
                for (int j = 0; j < 4; j++)
                    if (c0 + j > r0 + i) s[i][j] = -1e30f;
        }

        // Row max (local then width-16 shuffle reduce).
        float rmax[4];
#pragma unroll
        for (int i = 0; i < 4; i++) {
            rmax[i] = fmaxf(fmaxf(s[i][0], s[i][1]), fmaxf(s[i][2], s[i][3]));
        }
#pragma unroll
        for (int off = 8; off >= 1; off >>= 1) {
#pragma unroll
            for (int i = 0; i < 4; i++)
                rmax[i] = fmaxf(rmax[i], __shfl_xor_sync(0xffffffffu, rmax[i], off));
        }

        float alpha[4], rsum[4];
#pragma unroll
        for (int i = 0; i < 4; i++) {
            float mn = fmaxf(m_i[i], rmax[i]);
            alpha[i] = __expf(m_i[i] - mn);
            m_i[i]   = mn;
            float rs = 0.0f;
#pragma unroll
            for (int j = 0; j < 4; j++) {
                float p = __expf(s[i][j] - mn);
                s[i][j] = p;
                rs += p;
            }
            rsum[i] = rs;
        }
#pragma unroll
        for (int off = 8; off >= 1; off >>= 1) {
#pragma unroll
            for (int i = 0; i < 4; i++)
                rsum[i] += __shfl_xor_sync(0xffffffffu, rsum[i], off);
        }
#pragma unroll
        for (int i = 0; i < 4; i++) {
            l_i[i] = l_i[i] * alpha[i] + rsum[i];
#pragma unroll
            for (int j = 0; j < 4; j++) acc[i][j] *= alpha[i];
        }

        // Publish P for the cross-thread PV GEMM.
#pragma unroll
        for (int i = 0; i < 4; i++) {
            float4 p4;
            p4.x = s[i][0]; p4.y = s[i][1]; p4.z = s[i][2]; p4.w = s[i][3];
            *(float4*)(Ps + (r0 + i) * 64 + c0) = p4;
        }
        __syncthreads();

        // O += P @ V   (thread owns rows r0.., d-cols c0..)
#pragma unroll 8
        for (int c = 0; c < 64; c++) {
            float4 v4 = *(float4*)(Vs + c * 64 + c0);
            float vr[4] = {v4.x, v4.y, v4.z, v4.w};
            float p0 = Ps[(r0 + 0) * 64 + c];
            float p1 = Ps[(r0 + 1) * 64 + c];
            float p2 = Ps[(r0 + 2) * 64 + c];
            float p3 = Ps[(r0 + 3) * 64 + c];
#pragma unroll
            for (int j = 0; j < 4; j++) {
                acc[0][j] += p0 * vr[j];
                acc[1][j] += p1 * vr[j];
                acc[2][j] += p2 * vr[j];
                acc[3][j] += p3 * vr[j];
            }
        }
    }

    // Epilogue: O /= l, write to [B,T,C] layout (head h occupies cols h*64..)
#pragma unroll
    for (int i = 0; i < 4; i++) {
        float inv = 1.0f / l_i[i];
        float4 o;
        o.x = acc[i][0] * inv;
        o.y = acc[i][1] * inv;
        o.z = acc[i][2] * inv;
        o.w = acc[i][3] * inv;
        *(float4*)(out + (size_t)(b * T_ + qt * 64 + r0 + i) * C_ + h * 64 + c0) = o;
    }
}

// ---------------------------------------------------------------------------
// Launcher
// ---------------------------------------------------------------------------
extern "C" void kernel_launch(void* const* d_in, const int* in_sizes, int n_in,
                              void* d_out, int out_size)
{
    (void)in_sizes; (void)n_in; (void)out_size;
    const float* x      = (const float*)d_in[0];   // [B,T,C]
    const float* w_attn = (const float*)d_in[1];   // [C,3C]
    const float* b_attn = (const float*)d_in[2];   // [3C]
    const float* w_proj = (const float*)d_in[3];   // [C,C]
    const float* b_proj = (const float*)d_in[4];   // [C]
    float* out = (float*)d_out;                    // [B,T,C]

    void* qkv_p = nullptr;
    void* att_p = nullptr;
    cudaGetSymbolAddress(&qkv_p, g_qkv);
    cudaGetSymbolAddress(&att_p, g_att);
    float* qkv = (float*)qkv_p;
    float* att = (float*)att_p;

    // Stage 1: qkv = x @ w_attn + b_attn
    {
        dim3 grid(C3_ / 64, (B_ * T_) / 64);
        sgemm_bias<<<grid, 256>>>(x, w_attn, b_attn, qkv, B_ * T_, C3_, C_);
    }

    // Stage 2: causal flash attention
    {
        cudaFuncSetAttribute(flash_attn,
                             cudaFuncAttributeMaxDynamicSharedMemorySize, 65536);
        dim3 grid(T_ / 64, H_, B_);
        flash_attn<<<grid, 256, 65536>>>(qkv, att);
    }

    // Stage 3: out = att @ w_proj + b_proj
    {
        dim3 grid(C_ / 64, (B_ * T_) / 64);
        sgemm_bias<<<grid, 256>>>(att, w_proj, b_proj, out, B_ * T_, C_, C_);
    }
}

// round 4
// speedup vs baseline: 1.5684x; 1.5684x over previous
#include <cuda_runtime.h>
#include <cuda_bf16.h>
#include <cstdint>

// Problem constants
#define B_   4
#define T_   2048
#define C_   1024
#define H_   16
#define C3_  3072
#define MTOT (B_ * T_)   // 8192

// Scratch (__device__ globals; no allocations allowed)
__device__ float         g_qkv[(size_t)MTOT * C3_];         // fp32 [M][3C]
__device__ __nv_bfloat16 g_xhi[(size_t)MTOT * C_];
__device__ __nv_bfloat16 g_xlo[(size_t)MTOT * C_];
__device__ __nv_bfloat16 g_wahi[(size_t)C3_ * C_];          // w_attn^T [N][K]
__device__ __nv_bfloat16 g_walo[(size_t)C3_ * C_];
__device__ __nv_bfloat16 g_wphi[(size_t)C_ * C_];           // w_proj^T [N][K]
__device__ __nv_bfloat16 g_wplo[(size_t)C_ * C_];
__device__ __nv_bfloat16 g_atthi[(size_t)MTOT * C_];
__device__ __nv_bfloat16 g_attlo[(size_t)MTOT * C_];

// ===========================================================================
// sm_100-base PTX helpers (NO 'a'-suffix features)
// ===========================================================================
__device__ __forceinline__ uint32_t smem_u32(const void* p) {
    uint32_t a;
    asm("{ .reg .u64 t; cvta.to.shared.u64 t, %1; cvt.u32.u64 %0, t; }"
        : "=r"(a) : "l"(p));
    return a;
}

__device__ __forceinline__ void cp16(uint32_t dst, const void* src) {
    asm volatile("cp.async.cg.shared.global [%0], [%1], 16;"
                 :: "r"(dst), "l"(src) : "memory");
}
#define CP_COMMIT() asm volatile("cp.async.commit_group;" ::: "memory")
#define CP_WAIT(n)  asm volatile("cp.async.wait_group %0;" :: "n"(n) : "memory")

__device__ __forceinline__ void ldsm_x4(uint32_t* r, uint32_t addr) {
    asm volatile("ldmatrix.sync.aligned.m8n8.x4.shared.b16 {%0,%1,%2,%3}, [%4];"
                 : "=r"(r[0]), "=r"(r[1]), "=r"(r[2]), "=r"(r[3]) : "r"(addr));
}

__device__ __forceinline__ void mma_bf16(float* c, const uint32_t* a,
                                         const uint32_t* b) {
    asm volatile(
        "mma.sync.aligned.m16n8k16.row.col.f32.bf16.bf16.f32 "
        "{%0,%1,%2,%3}, {%4,%5,%6,%7}, {%8,%9}, {%0,%1,%2,%3};"
        : "+f"(c[0]), "+f"(c[1]), "+f"(c[2]), "+f"(c[3])
        : "r"(a[0]), "r"(a[1]), "r"(a[2]), "r"(a[3]), "r"(b[0]), "r"(b[1]));
}

__device__ __forceinline__ uint32_t pack_bf16(__nv_bfloat16 a, __nv_bfloat16 b) {
    return (uint32_t)__bfloat16_as_ushort(a) |
           ((uint32_t)__bfloat16_as_ushort(b) << 16);
}

// ===========================================================================
// Prep: fp32 [R][K] -> bf16 hi/lo same layout (vectorized)
// ===========================================================================
__global__ __launch_bounds__(256) void split_rows(
    const float* __restrict__ in,
    __nv_bfloat16* __restrict__ hi, __nv_bfloat16* __restrict__ lo)
{
    size_t i = ((size_t)blockIdx.x * 256 + threadIdx.x) * 4;
    float4 v = *(const float4*)(in + i);
    __nv_bfloat16 h0 = __float2bfloat16(v.x);
    __nv_bfloat16 h1 = __float2bfloat16(v.y);
    __nv_bfloat16 h2 = __float2bfloat16(v.z);
    __nv_bfloat16 h3 = __float2bfloat16(v.w);
    __nv_bfloat16 l0 = __float2bfloat16(v.x - __bfloat162float(h0));
    __nv_bfloat16 l1 = __float2bfloat16(v.y - __bfloat162float(h1));
    __nv_bfloat16 l2 = __float2bfloat16(v.z - __bfloat162float(h2));
    __nv_bfloat16 l3 = __float2bfloat16(v.w - __bfloat162float(h3));
    uint2 ph = {pack_bf16(h0, h1), pack_bf16(h2, h3)};
    uint2 pl = {pack_bf16(l0, l1), pack_bf16(l2, l3)};
    *(uint2*)(hi + i) = ph;
    *(uint2*)(lo + i) = pl;
}

// ===========================================================================
// Prep: fp32 [K][N] -> bf16 hi/lo transposed [N][K]
// ===========================================================================
__global__ __launch_bounds__(256) void transpose_split(
    const float* __restrict__ in,
    __nv_bfloat16* __restrict__ hi, __nv_bfloat16* __restrict__ lo,
    int K, int N)
{
    __shared__ float t[32][33];
    const int n0 = blockIdx.x * 32;
    const int k0 = blockIdx.y * 32;
    const int tx = threadIdx.x;
    const int ty = threadIdx.y;
#pragma unroll
    for (int j = 0; j < 32; j += 8)
        t[ty + j][tx] = in[(size_t)(k0 + ty + j) * N + n0 + tx];
    __syncthreads();
#pragma unroll
    for (int j = 0; j < 32; j += 8) {
        float v = t[tx][ty + j];
        __nv_bfloat16 h = __float2bfloat16(v);
        __nv_bfloat16 l = __float2bfloat16(v - __bfloat162float(h));
        size_t o = (size_t)(n0 + ty + j) * K + k0 + tx;
        hi[o] = h;
        lo[o] = l;
    }
}

// ===========================================================================
// bf16x3 tensor-core GEMM: C[M][N] = A[M][K] @ W^T[N][K]^T + bias[N]
// A, Bt given as bf16 hi/lo, both [row][K] (K contiguous).
// CTA tile 128x128, BK=32, 8 warps (64M x 32N each), cp.async double buffer.
// ===========================================================================
#define PITCH_B   80                    // bytes per smem row (32 bf16 + 8 pad)
#define TILE_B    (128 * PITCH_B)       // 10240 B
#define STAGE_B   (4 * TILE_B)          // Ahi,Alo,Bhi,Blo = 40960 B
#define GEMM_SMEM (2 * STAGE_B)         // 81920 B

__global__ __launch_bounds__(256) void gemm_bf16x3(
    const __nv_bfloat16* __restrict__ Ahi, const __nv_bfloat16* __restrict__ Alo,
    const __nv_bfloat16* __restrict__ Bhi, const __nv_bfloat16* __restrict__ Blo,
    const float* __restrict__ bias, float* __restrict__ Cout,
    int M, int N, int K)
{
    extern __shared__ char smem[];
    const uint32_t sbase = smem_u32(smem);
    const int tid  = threadIdx.x;
    const int wid  = tid >> 5;
    const int lane = tid & 31;
    const int m0 = blockIdx.y * 128;
    const int n0 = blockIdx.x * 128;
    const int wm = (wid & 1) * 64;       // warp M offset in tile
    const int wn = (wid >> 1) * 32;      // warp N offset in tile

    const int nchunks = K >> 5;

    // ---- async stage loader: chunk kc -> buffer (kc & 1) ----
    auto load_stage = [&](int buf, int kc) {
        const int k0 = kc << 5;
        const uint32_t base = sbase + buf * STAGE_B;
#pragma unroll
        for (int i = 0; i < 2; i++) {
            int idx = tid + i * 256;           // 0..511
            int row = idx >> 2;                // 0..127
            int ch  = idx & 3;                 // 16B chunk
            uint32_t soff = (uint32_t)row * PITCH_B + ch * 16;
            size_t ga = (size_t)(m0 + row) * K + k0 + ch * 8;
            size_t gb = (size_t)(n0 + row) * K + k0 + ch * 8;
            cp16(base + soff,              Ahi + ga);
            cp16(base + TILE_B + soff,     Alo + ga);
            cp16(base + 2 * TILE_B + soff, Bhi + gb);
            cp16(base + 3 * TILE_B + soff, Blo + gb);
        }
    };

    float acc[4][4][4];
#pragma unroll
    for (int a = 0; a < 4; a++)
#pragma unroll
        for (int b = 0; b < 4; b++)
#pragma unroll
            for (int c = 0; c < 4; c++) acc[a][b][c] = 0.0f;

    load_stage(0, 0); CP_COMMIT();
    load_stage(1, 1); CP_COMMIT();

    const uint32_t lrow  = lane & 15;
    const uint32_t lk8b  = ((lane >> 4) * 8) * 2;   // byte offset of k-half

    for (int c = 0; c < nchunks; c++) {
        if (c + 1 < nchunks) { CP_WAIT(1); } else { CP_WAIT(0); }
        __syncthreads();

        const uint32_t st   = sbase + (c & 1) * STAGE_B;
        const uint32_t sAhi = st;
        const uint32_t sAlo = st + TILE_B;
        const uint32_t sBhi = st + 2 * TILE_B;
        const uint32_t sBlo = st + 3 * TILE_B;

#pragma unroll
        for (int ks = 0; ks < 2; ks++) {
            const uint32_t kb = (uint32_t)(ks * 32) + lk8b;  // 16 bf16 = 32B

            uint32_t Bh[4][2], Bl[4][2];
            {
                uint32_t r[4];
                ldsm_x4(r, sBhi + (wn + lrow) * PITCH_B + kb);
                Bh[0][0] = r[0]; Bh[1][0] = r[1]; Bh[0][1] = r[2]; Bh[1][1] = r[3];
                ldsm_x4(r, sBhi + (wn + 16 + lrow) * PITCH_B + kb);
                Bh[2][0] = r[0]; Bh[3][0] = r[1]; Bh[2][1] = r[2]; Bh[3][1] = r[3];
                ldsm_x4(r, sBlo + (wn + lrow) * PITCH_B + kb);
                Bl[0][0] = r[0]; Bl[1][0] = r[1]; Bl[0][1] = r[2]; Bl[1][1] = r[3];
                ldsm_x4(r, sBlo + (wn + 16 + lrow) * PITCH_B + kb);
                Bl[2][0] = r[0]; Bl[3][0] = r[1]; Bl[2][1] = r[2]; Bl[3][1] = r[3];
            }

#pragma unroll
            for (int mt = 0; mt < 4; mt++) {
                uint32_t Ah[4], Al[4];
                ldsm_x4(Ah, sAhi + (wm + mt * 16 + lrow) * PITCH_B + kb);
                ldsm_x4(Al, sAlo + (wm + mt * 16 + lrow) * PITCH_B + kb);
#pragma unroll
                for (int nt = 0; nt < 4; nt++) {
                    float* cc = &acc[mt][nt][0];
                    mma_bf16(cc, Ah, Bh[nt]);
                    mma_bf16(cc, Ah, Bl[nt]);
                    mma_bf16(cc, Al, Bh[nt]);
                }
            }
        }
        __syncthreads();

        if (c + 2 < nchunks) { load_stage(c & 1, c + 2); CP_COMMIT(); }
    }

    // ---- epilogue: add bias, store fp32 ----
    const int lr = lane >> 2;
    const int lc = (lane & 3) * 2;
#pragma unroll
    for (int nt = 0; nt < 4; nt++) {
        const int col = n0 + wn + nt * 8 + lc;
        float2 bv = *(const float2*)(bias + col);
#pragma unroll
        for (int mt = 0; mt < 4; mt++) {
            const int mrow = m0 + wm + mt * 16 + lr;
            float2 o0 = {acc[mt][nt][0] + bv.x, acc[mt][nt][1] + bv.y};
            float2 o1 = {acc[mt][nt][2] + bv.x, acc[mt][nt][3] + bv.y};
            *(float2*)(Cout + (size_t)mrow * N + col) = o0;
            *(float2*)(Cout + (size_t)(mrow + 8) * N + col) = o1;
        }
    }
}

// ---------------------------------------------------------------------------
// Causal flash attention, fp32 SIMT. Epilogue now writes bf16 hi/lo of att.
// ---------------------------------------------------------------------------
__global__ __launch_bounds__(256) void flash_attn(
    const float* __restrict__ qkv,
    __nv_bfloat16* __restrict__ ohi, __nv_bfloat16* __restrict__ olo)
{
    const int qt = blockIdx.x;
    const int h  = blockIdx.y;
    const int b  = blockIdx.z;

    extern __shared__ float sm[];
    float* Qt = sm;
    float* Kt = Qt + 64 * 64;
    float* Vs = Kt + 64 * 64;
    float* Ps = Vs + 64 * 64;

    const int tid = threadIdx.x;
    const int ty  = tid >> 4;
    const int tx  = tid & 15;
    const int r0  = ty * 4;
    const int c0  = tx * 4;

    const float scale = 0.125f;

    {
        const float* qbase = qkv + ((size_t)(b * T_ + qt * 64) * C3_) + h * 64;
#pragma unroll
        for (int it = 0; it < 4; it++) {
            int i  = tid + it * 256;
            int r  = i >> 4;
            int d4 = (i & 15) * 4;
            float4 v = *(const float4*)(qbase + (size_t)r * C3_ + d4);
            Qt[(d4 + 0) * 64 + r] = v.x * scale;
            Qt[(d4 + 1) * 64 + r] = v.y * scale;
            Qt[(d4 + 2) * 64 + r] = v.z * scale;
            Qt[(d4 + 3) * 64 + r] = v.w * scale;
        }
    }

    float m_i[4], l_i[4], acc[4][4];
#pragma unroll
    for (int i = 0; i < 4; i++) {
        m_i[i] = -1e30f;
        l_i[i] = 0.0f;
#pragma unroll
        for (int j = 0; j < 4; j++) acc[i][j] = 0.0f;
    }

    for (int kt = 0; kt <= qt; kt++) {
        __syncthreads();

        {
            const float* kbase = qkv + ((size_t)(b * T_ + kt * 64) * C3_) + C_ + h * 64;
            const float* vbase = kbase + C_;
#pragma unroll
            for (int it = 0; it < 4; it++) {
                int i  = tid + it * 256;
                int c  = i >> 4;
                int d4 = (i & 15) * 4;
                float4 kv = *(const float4*)(kbase + (size_t)c * C3_ + d4);
                Kt[(d4 + 0) * 64 + c] = kv.x;
                Kt[(d4 + 1) * 64 + c] = kv.y;
                Kt[(d4 + 2) * 64 + c] = kv.z;
                Kt[(d4 + 3) * 64 + c] = kv.w;
                *(float4*)(Vs + c * 64 + d4) =
                    *(const float4*)(vbase + (size_t)c * C3_ + d4);
            }
        }
        __syncthreads();

        float s[4][4] = {};
#pragma unroll 16
        for (int d = 0; d < 64; d++) {
            float4 q4 = *(float4*)(Qt + d * 64 + r0);
            float4 k4 = *(float4*)(Kt + d * 64 + c0);
            float qr[4] = {q4.x, q4.y, q4.z, q4.w};
            float kr[4] = {k4.x, k4.y, k4.z, k4.w};
#pragma unroll
            for (int i = 0; i < 4; i++)
#pragma unroll
                for (int j = 0; j < 4; j++)
                    s[i][j] += qr[i] * kr[j];
        }

        if (kt == qt) {
#pragma unroll
            for (int i = 0; i < 4; i++)
#pragma unroll
                for (int j = 0; j < 4; j++)
                    if (c0 + j > r0 + i) s[i][j] = -1e30f;
        }

        float rmax[4];
#pragma unroll
        for (int i = 0; i < 4; i++)
            rmax[i] = fmaxf(fmaxf(s[i][0], s[i][1]), fmaxf(s[i][2], s[i][3]));
#pragma unroll
        for (int off = 8; off >= 1; off >>= 1) {
#pragma unroll
            for (int i = 0; i < 4; i++)
                rmax[i] = fmaxf(rmax[i], __shfl_xor_sync(0xffffffffu, rmax[i], off));
        }

        float alpha[4], rsum[4];
#pragma unroll
        for (int i = 0; i < 4; i++) {
            float mn = fmaxf(m_i[i], rmax[i]);
            alpha[i] = __expf(m_i[i] - mn);
            m_i[i]   = mn;
            float rs = 0.0f;
#pragma unroll
            for (int j = 0; j < 4; j++) {
                float p = __expf(s[i][j] - mn);
                s[i][j] = p;
                rs += p;
            }
            rsum[i] = rs;
        }
#pragma unroll
        for (int off = 8; off >= 1; off >>= 1) {
#pragma unroll
            for (int i = 0; i < 4; i++)
                rsum[i] += __shfl_xor_sync(0xffffffffu, rsum[i], off);
        }
#pragma unroll
        for (int i = 0; i < 4; i++) {
            l_i[i] = l_i[i] * alpha[i] + rsum[i];
#pragma unroll
            for (int j = 0; j < 4; j++) acc[i][j] *= alpha[i];
        }

#pragma unroll
        for (int i = 0; i < 4; i++) {
            float4 p4;
            p4.x = s[i][0]; p4.y = s[i][1]; p4.z = s[i][2]; p4.w = s[i][3];
            *(float4*)(Ps + (r0 + i) * 64 + c0) = p4;
        }
        __syncthreads();

#pragma unroll 8
        for (int c = 0; c < 64; c++) {
            float4 v4 = *(float4*)(Vs + c * 64 + c0);
            float vr[4] = {v4.x, v4.y, v4.z, v4.w};
            float p0 = Ps[(r0 + 0) * 64 + c];
            float p1 = Ps[(r0 + 1) * 64 + c];
            float p2 = Ps[(r0 + 2) * 64 + c];
            float p3 = Ps[(r0 + 3) * 64 + c];
#pragma unroll
            for (int j = 0; j < 4; j++) {
                acc[0][j] += p0 * vr[j];
                acc[1][j] += p1 * vr[j];
                acc[2][j] += p2 * vr[j];
                acc[3][j] += p3 * vr[j];
            }
        }
    }

    // Epilogue: normalize, split into bf16 hi/lo, store
#pragma unroll
    for (int i = 0; i < 4; i++) {
        float inv = 1.0f / l_i[i];
        float o[4];
#pragma unroll
        for (int j = 0; j < 4; j++) o[j] = acc[i][j] * inv;
        __nv_bfloat16 hh[4], ll[4];
#pragma unroll
        for (int j = 0; j < 4; j++) {
            hh[j] = __float2bfloat16(o[j]);
            ll[j] = __float2bfloat16(o[j] - __bfloat162float(hh[j]));
        }
        size_t ob = (size_t)(b * T_ + qt * 64 + r0 + i) * C_ + h * 64 + c0;
        uint2 ph = {pack_bf16(hh[0], hh[1]), pack_bf16(hh[2], hh[3])};
        uint2 pl = {pack_bf16(ll[0], ll[1]), pack_bf16(ll[2], ll[3])};
        *(uint2*)(ohi + ob) = ph;
        *(uint2*)(olo + ob) = pl;
    }
}

// ---------------------------------------------------------------------------
// Launcher
// ---------------------------------------------------------------------------
extern "C" void kernel_launch(void* const* d_in, const int* in_sizes, int n_in,
                              void* d_out, int out_size)
{
    (void)in_sizes; (void)n_in; (void)out_size;
    const float* x      = (const float*)d_in[0];
    const float* w_attn = (const float*)d_in[1];
    const float* b_attn = (const float*)d_in[2];
    const float* w_proj = (const float*)d_in[3];
    const float* b_proj = (const float*)d_in[4];
    float* out = (float*)d_out;

    void *qkv_p, *xhi_p, *xlo_p, *wahi_p, *walo_p, *wphi_p, *wplo_p, *athi_p, *atlo_p;
    cudaGetSymbolAddress(&qkv_p,  g_qkv);
    cudaGetSymbolAddress(&xhi_p,  g_xhi);
    cudaGetSymbolAddress(&xlo_p,  g_xlo);
    cudaGetSymbolAddress(&wahi_p, g_wahi);
    cudaGetSymbolAddress(&walo_p, g_walo);
    cudaGetSymbolAddress(&wphi_p, g_wphi);
    cudaGetSymbolAddress(&wplo_p, g_wplo);
    cudaGetSymbolAddress(&athi_p, g_atthi);
    cudaGetSymbolAddress(&atlo_p, g_attlo);

    cudaFuncSetAttribute(gemm_bf16x3,
                         cudaFuncAttributeMaxDynamicSharedMemorySize, GEMM_SMEM);
    cudaFuncSetAttribute(flash_attn,
                         cudaFuncAttributeMaxDynamicSharedMemorySize, 65536);

    // Prep: split x; transpose+split weights
    {
        size_t n4 = (size_t)MTOT * C_ / 4;
        split_rows<<<(unsigned)(n4 / 256), 256>>>(
            x, (__nv_bfloat16*)xhi_p, (__nv_bfloat16*)xlo_p);

        dim3 ga(C3_ / 32, C_ / 32);
        transpose_split<<<ga, dim3(32, 8)>>>(
            w_attn, (__nv_bfloat16*)wahi_p, (__nv_bfloat16*)walo_p, C_, C3_);

        dim3 gp(C_ / 32, C_ / 32);
        transpose_split<<<gp, dim3(32, 8)>>>(
            w_proj, (__nv_bfloat16*)wphi_p, (__nv_bfloat16*)wplo_p, C_, C_);
    }

    // Stage 1: qkv = x @ w_attn + b_attn
    {
        dim3 grid(C3_ / 128, MTOT / 128);
        gemm_bf16x3<<<grid, 256, GEMM_SMEM>>>(
            (const __nv_bfloat16*)xhi_p, (const __nv_bfloat16*)xlo_p,
            (const __nv_bfloat16*)wahi_p, (const __nv_bfloat16*)walo_p,
            b_attn, (float*)qkv_p, MTOT, C3_, C_);
    }

    // Stage 2: flash attention -> att (bf16 hi/lo)
    {
        dim3 grid(T_ / 64, H_, B_);
        flash_attn<<<grid, 256, 65536>>>(
            (const float*)qkv_p,
            (__nv_bfloat16*)athi_p, (__nv_bfloat16*)atlo_p);
    }

    // Stage 3: out = att @ w_proj + b_proj
    {
        dim3 grid(C_ / 128, MTOT / 128);
        gemm_bf16x3<<<grid, 256, GEMM_SMEM>>>(
            (const __nv_bfloat16*)athi_p, (const __nv_bfloat16*)atlo_p,
            (const __nv_bfloat16*)wphi_p, (const __nv_bfloat16*)wplo_p,
            b_proj, out, MTOT, C_, C_);
    }
}

// round 5
// speedup vs baseline: 2.6926x; 1.7168x over previous
#include <cuda_runtime.h>
#include <cuda_bf16.h>
#include <cstdint>

// Problem constants
#define B_   4
#define T_   2048
#define C_   1024
#define H_   16
#define C3_  3072
#define MTOT (B_ * T_)   // 8192

// Scratch (__device__ globals; no allocations allowed)
__device__ __nv_bfloat16 g_xhi[(size_t)MTOT * C_];
__device__ __nv_bfloat16 g_xlo[(size_t)MTOT * C_];
__device__ __nv_bfloat16 g_wahi[(size_t)C3_ * C_];          // w_attn^T [N][K]
__device__ __nv_bfloat16 g_walo[(size_t)C3_ * C_];
__device__ __nv_bfloat16 g_wphi[(size_t)C_ * C_];           // w_proj^T [N][K]
__device__ __nv_bfloat16 g_wplo[(size_t)C_ * C_];
__device__ __nv_bfloat16 g_atthi[(size_t)MTOT * C_];
__device__ __nv_bfloat16 g_attlo[(size_t)MTOT * C_];
// Q/K/V in [b][h][t][d] layout, bf16 hi/lo (Q pre-scaled by 0.125)
#define QKV_ELEMS ((size_t)B_ * H_ * T_ * 64)
__device__ __nv_bfloat16 g_qh[QKV_ELEMS];
__device__ __nv_bfloat16 g_ql[QKV_ELEMS];
__device__ __nv_bfloat16 g_kh[QKV_ELEMS];
__device__ __nv_bfloat16 g_kl[QKV_ELEMS];
__device__ __nv_bfloat16 g_vh[QKV_ELEMS];
__device__ __nv_bfloat16 g_vl[QKV_ELEMS];

// ===========================================================================
// sm_100-base PTX helpers
// ===========================================================================
__device__ __forceinline__ uint32_t smem_u32(const void* p) {
    uint32_t a;
    asm("{ .reg .u64 t; cvta.to.shared.u64 t, %1; cvt.u32.u64 %0, t; }"
        : "=r"(a) : "l"(p));
    return a;
}

__device__ __forceinline__ void cp16(uint32_t dst, const void* src) {
    asm volatile("cp.async.cg.shared.global [%0], [%1], 16;"
                 :: "r"(dst), "l"(src) : "memory");
}
#define CP_COMMIT() asm volatile("cp.async.commit_group;" ::: "memory")
#define CP_WAIT(n)  asm volatile("cp.async.wait_group %0;" :: "n"(n) : "memory")

__device__ __forceinline__ void ldsm_x4(uint32_t* r, uint32_t addr) {
    asm volatile("ldmatrix.sync.aligned.m8n8.x4.shared.b16 {%0,%1,%2,%3}, [%4];"
                 : "=r"(r[0]), "=r"(r[1]), "=r"(r[2]), "=r"(r[3]) : "r"(addr));
}
__device__ __forceinline__ void ldsm_x4_t(uint32_t* r, uint32_t addr) {
    asm volatile("ldmatrix.sync.aligned.m8n8.x4.trans.shared.b16 {%0,%1,%2,%3}, [%4];"
                 : "=r"(r[0]), "=r"(r[1]), "=r"(r[2]), "=r"(r[3]) : "r"(addr));
}

__device__ __forceinline__ void mma_bf16(float* c, const uint32_t* a,
                                         const uint32_t* b) {
    asm volatile(
        "mma.sync.aligned.m16n8k16.row.col.f32.bf16.bf16.f32 "
        "{%0,%1,%2,%3}, {%4,%5,%6,%7}, {%8,%9}, {%0,%1,%2,%3};"
        : "+f"(c[0]), "+f"(c[1]), "+f"(c[2]), "+f"(c[3])
        : "r"(a[0]), "r"(a[1]), "r"(a[2]), "r"(a[3]), "r"(b[0]), "r"(b[1]));
}

__device__ __forceinline__ uint32_t pack_bf16(__nv_bfloat16 a, __nv_bfloat16 b) {
    return (uint32_t)__bfloat16_as_ushort(a) |
           ((uint32_t)__bfloat16_as_ushort(b) << 16);
}
__device__ __forceinline__ uint32_t pack_hi(float x, float y) {
    return pack_bf16(__float2bfloat16(x), __float2bfloat16(y));
}
__device__ __forceinline__ uint32_t pack_lo(float x, float y) {
    __nv_bfloat16 hx = __float2bfloat16(x), hy = __float2bfloat16(y);
    return pack_bf16(__float2bfloat16(x - __bfloat162float(hx)),
                     __float2bfloat16(y - __bfloat162float(hy)));
}

// ===========================================================================
// Prep kernels
// ===========================================================================
__global__ __launch_bounds__(256) void split_rows(
    const float* __restrict__ in,
    __nv_bfloat16* __restrict__ hi, __nv_bfloat16* __restrict__ lo)
{
    size_t i = ((size_t)blockIdx.x * 256 + threadIdx.x) * 4;
    float4 v = *(const float4*)(in + i);
    uint2 ph = {pack_hi(v.x, v.y), pack_hi(v.z, v.w)};
    uint2 pl = {pack_lo(v.x, v.y), pack_lo(v.z, v.w)};
    *(uint2*)(hi + i) = ph;
    *(uint2*)(lo + i) = pl;
}

__global__ __launch_bounds__(256) void transpose_split(
    const float* __restrict__ in,
    __nv_bfloat16* __restrict__ hi, __nv_bfloat16* __restrict__ lo,
    int K, int N)
{
    __shared__ float t[32][33];
    const int n0 = blockIdx.x * 32;
    const int k0 = blockIdx.y * 32;
    const int tx = threadIdx.x;
    const int ty = threadIdx.y;
#pragma unroll
    for (int j = 0; j < 32; j += 8)
        t[ty + j][tx] = in[(size_t)(k0 + ty + j) * N + n0 + tx];
    __syncthreads();
#pragma unroll
    for (int j = 0; j < 32; j += 8) {
        float v = t[tx][ty + j];
        __nv_bfloat16 h = __float2bfloat16(v);
        __nv_bfloat16 l = __float2bfloat16(v - __bfloat162float(h));
        size_t o = (size_t)(n0 + ty + j) * K + k0 + tx;
        hi[o] = h;
        lo[o] = l;
    }
}

// ===========================================================================
// bf16x3 tensor-core GEMM. mode 0: fp32 out + bias. mode 1: split-store QKV.
// ===========================================================================
#define PITCH_B   80
#define TILE_B    (128 * PITCH_B)
#define STAGE_B   (4 * TILE_B)
#define GEMM_SMEM (2 * STAGE_B)

__global__ __launch_bounds__(256) void gemm_bf16x3(
    const __nv_bfloat16* __restrict__ Ahi, const __nv_bfloat16* __restrict__ Alo,
    const __nv_bfloat16* __restrict__ Bhi, const __nv_bfloat16* __restrict__ Blo,
    const float* __restrict__ bias, float* __restrict__ Cout,
    int M, int N, int K, int qkv_mode,
    __nv_bfloat16* qh, __nv_bfloat16* ql,
    __nv_bfloat16* kh, __nv_bfloat16* kl,
    __nv_bfloat16* vh, __nv_bfloat16* vl)
{
    extern __shared__ char smem[];
    const uint32_t sbase = smem_u32(smem);
    const int tid  = threadIdx.x;
    const int wid  = tid >> 5;
    const int lane = tid & 31;
    const int m0 = blockIdx.y * 128;
    const int n0 = blockIdx.x * 128;
    const int wm = (wid & 1) * 64;
    const int wn = (wid >> 1) * 32;

    const int nchunks = K >> 5;

    auto load_stage = [&](int buf, int kc) {
        const int k0 = kc << 5;
        const uint32_t base = sbase + buf * STAGE_B;
#pragma unroll
        for (int i = 0; i < 2; i++) {
            int idx = tid + i * 256;
            int row = idx >> 2;
            int ch  = idx & 3;
            uint32_t soff = (uint32_t)row * PITCH_B + ch * 16;
            size_t ga = (size_t)(m0 + row) * K + k0 + ch * 8;
            size_t gb = (size_t)(n0 + row) * K + k0 + ch * 8;
            cp16(base + soff,              Ahi + ga);
            cp16(base + TILE_B + soff,     Alo + ga);
            cp16(base + 2 * TILE_B + soff, Bhi + gb);
            cp16(base + 3 * TILE_B + soff, Blo + gb);
        }
    };

    float acc[4][4][4];
#pragma unroll
    for (int a = 0; a < 4; a++)
#pragma unroll
        for (int b = 0; b < 4; b++)
#pragma unroll
            for (int c = 0; c < 4; c++) acc[a][b][c] = 0.0f;

    load_stage(0, 0); CP_COMMIT();
    load_stage(1, 1); CP_COMMIT();

    const uint32_t lrow = lane & 15;
    const uint32_t lkb  = (lane >> 4) * 16;

    for (int c = 0; c < nchunks; c++) {
        if (c + 1 < nchunks) { CP_WAIT(1); } else { CP_WAIT(0); }
        __syncthreads();

        const uint32_t st   = sbase + (c & 1) * STAGE_B;
        const uint32_t sAhi = st;
        const uint32_t sAlo = st + TILE_B;
        const uint32_t sBhi = st + 2 * TILE_B;
        const uint32_t sBlo = st + 3 * TILE_B;

#pragma unroll
        for (int ks = 0; ks < 2; ks++) {
            const uint32_t kb = (uint32_t)(ks * 32) + lkb;

            uint32_t Bh[4][2], Bl[4][2];
            {
                uint32_t r[4];
                ldsm_x4(r, sBhi + (wn + lrow) * PITCH_B + kb);
                Bh[0][0] = r[0]; Bh[1][0] = r[1]; Bh[0][1] = r[2]; Bh[1][1] = r[3];
                ldsm_x4(r, sBhi + (wn + 16 + lrow) * PITCH_B + kb);
                Bh[2][0] = r[0]; Bh[3][0] = r[1]; Bh[2][1] = r[2]; Bh[3][1] = r[3];
                ldsm_x4(r, sBlo + (wn + lrow) * PITCH_B + kb);
                Bl[0][0] = r[0]; Bl[1][0] = r[1]; Bl[0][1] = r[2]; Bl[1][1] = r[3];
                ldsm_x4(r, sBlo + (wn + 16 + lrow) * PITCH_B + kb);
                Bl[2][0] = r[0]; Bl[3][0] = r[1]; Bl[2][1] = r[2]; Bl[3][1] = r[3];
            }

#pragma unroll
            for (int mt = 0; mt < 4; mt++) {
                uint32_t Ah[4], Al[4];
                ldsm_x4(Ah, sAhi + (wm + mt * 16 + lrow) * PITCH_B + kb);
                ldsm_x4(Al, sAlo + (wm + mt * 16 + lrow) * PITCH_B + kb);
#pragma unroll
                for (int nt = 0; nt < 4; nt++) {
                    float* cc = &acc[mt][nt][0];
                    mma_bf16(cc, Ah, Bh[nt]);
                    mma_bf16(cc, Ah, Bl[nt]);
                    mma_bf16(cc, Al, Bh[nt]);
                }
            }
        }
        __syncthreads();

        if (c + 2 < nchunks) { load_stage(c & 1, c + 2); CP_COMMIT(); }
    }

    const int lr = lane >> 2;
    const int lc = (lane & 3) * 2;

    if (!qkv_mode) {
#pragma unroll
        for (int nt = 0; nt < 4; nt++) {
            const int col = n0 + wn + nt * 8 + lc;
            float2 bv = *(const float2*)(bias + col);
#pragma unroll
            for (int mt = 0; mt < 4; mt++) {
                const int mrow = m0 + wm + mt * 16 + lr;
                float2 o0 = {acc[mt][nt][0] + bv.x, acc[mt][nt][1] + bv.y};
                float2 o1 = {acc[mt][nt][2] + bv.x, acc[mt][nt][3] + bv.y};
                *(float2*)(Cout + (size_t)mrow * N + col) = o0;
                *(float2*)(Cout + (size_t)(mrow + 8) * N + col) = o1;
            }
        }
    } else {
        // split-store into Q/K/V [b][h][t][d], Q pre-scaled by 0.125
#pragma unroll
        for (int nt = 0; nt < 4; nt++) {
            const int col = n0 + wn + nt * 8 + lc;
            float2 bv = *(const float2*)(bias + col);
            const int sec = col >> 10;
            const int r   = col & 1023;
            const int hh  = r >> 6;
            const int dd  = r & 63;
            __nv_bfloat16* dh = (sec == 0) ? qh : (sec == 1) ? kh : vh;
            __nv_bfloat16* dl = (sec == 0) ? ql : (sec == 1) ? kl : vl;
            const float sc = (sec == 0) ? 0.125f : 1.0f;
#pragma unroll
            for (int mt = 0; mt < 4; mt++) {
                const int mrow = m0 + wm + mt * 16 + lr;
                const int bb = mrow >> 11;
                const int tt = mrow & 2047;
                size_t off = ((size_t)(bb * H_ + hh) * T_ + tt) * 64 + dd;
                float v0 = (acc[mt][nt][0] + bv.x) * sc;
                float v1 = (acc[mt][nt][1] + bv.y) * sc;
                float v2 = (acc[mt][nt][2] + bv.x) * sc;
                float v3 = (acc[mt][nt][3] + bv.y) * sc;
                *(uint32_t*)(dh + off)       = pack_hi(v0, v1);
                *(uint32_t*)(dl + off)       = pack_lo(v0, v1);
                *(uint32_t*)(dh + off + 512) = pack_hi(v2, v3);   // t+8
                *(uint32_t*)(dl + off + 512) = pack_lo(v2, v3);
            }
        }
    }
}

// ===========================================================================
// Tensor-core causal flash attention (bf16x3, FA2-style register P).
// CTA: 128 q rows x (h, b). 8 warps x 16 rows. KV tiles of 64, double buffer.
// ===========================================================================
#define FPITCH     144          // 72 bf16 per smem row; conflict-free ldmatrix
#define FSTAGE     36864        // 4 matrices * 64 rows * 144B
#define FKH        0
#define FKL        9216
#define FVH        18432
#define FVL        27648
#define FLASH_SMEM (2 * FSTAGE) // 73728

__global__ __launch_bounds__(256) void flash_attn_tc(
    const __nv_bfloat16* __restrict__ Qh, const __nv_bfloat16* __restrict__ Ql,
    const __nv_bfloat16* __restrict__ Kh, const __nv_bfloat16* __restrict__ Kl,
    const __nv_bfloat16* __restrict__ Vh, const __nv_bfloat16* __restrict__ Vl,
    __nv_bfloat16* __restrict__ ohi, __nv_bfloat16* __restrict__ olo)
{
    const int qt = blockIdx.x;
    const int h  = blockIdx.y;
    const int b  = blockIdx.z;
    const int q0 = qt * 128;
    const size_t gbase = (size_t)(b * H_ + h) * T_ * 64;

    extern __shared__ char smem[];
    const uint32_t sbase = smem_u32(smem);
    const int tid  = threadIdx.x;
    const int wid  = tid >> 5;
    const int lane = tid & 31;
    const uint32_t lrow = lane & 15;
    const uint32_t lkb  = (lane >> 4) * 16;
    const int wm = wid * 16;

    // ---- load Q tile (hi at sbase, lo at +18432), extract fragments ----
#pragma unroll
    for (int i = 0; i < 8; i++) {
        int idx = tid + i * 256;            // 0..2047
        int mat = idx >> 10;
        int rem = idx & 1023;
        int row = rem >> 3;
        int ch  = rem & 7;
        const __nv_bfloat16* src = (mat ? Ql : Qh) + gbase +
                                   (size_t)(q0 + row) * 64 + ch * 8;
        cp16(sbase + mat * 18432 + row * FPITCH + ch * 16, src);
    }
    CP_COMMIT(); CP_WAIT(0);
    __syncthreads();

    uint32_t qfh[4][4], qfl[4][4];
#pragma unroll
    for (int kc = 0; kc < 4; kc++) {
        ldsm_x4(qfh[kc], sbase +         (wm + lrow) * FPITCH + kc * 32 + lkb);
        ldsm_x4(qfl[kc], sbase + 18432 + (wm + lrow) * FPITCH + kc * 32 + lkb);
    }
    __syncthreads();

    auto load_kv = [&](int buf, int j) {
        const int kv0 = j * 64;
        const uint32_t st = sbase + buf * FSTAGE;
#pragma unroll
        for (int i = 0; i < 8; i++) {
            int idx = tid + i * 256;        // 0..2047
            int mat = idx >> 9;             // 0..3
            int rem = idx & 511;
            int row = rem >> 3;
            int ch  = rem & 7;
            const __nv_bfloat16* src =
                (mat == 0 ? Kh : mat == 1 ? Kl : mat == 2 ? Vh : Vl) +
                gbase + (size_t)(kv0 + row) * 64 + ch * 8;
            cp16(st + mat * 9216 + row * FPITCH + ch * 16, src);
        }
        CP_COMMIT();
    };

    const int nkv = 2 * qt + 2;
    load_kv(0, 0);
    load_kv(1, 1);

    const int rA = q0 + wm + (lane >> 2);   // global t of row half A
    const int rB = rA + 8;

    float mA = -1e30f, mB = -1e30f, lA = 0.0f, lB = 0.0f;
    float O[8][4];
#pragma unroll
    for (int nt = 0; nt < 8; nt++)
#pragma unroll
        for (int c = 0; c < 4; c++) O[nt][c] = 0.0f;

    for (int j = 0; j < nkv; j++) {
        if (j + 1 < nkv) { CP_WAIT(1); } else { CP_WAIT(0); }
        __syncthreads();

        const uint32_t st = sbase + (j & 1) * FSTAGE;
        const bool skip = (j * 64 > q0 + wm + 15);   // min col > warp max row

        if (!skip) {
            // ---- S = Q K^T (bf16x3) ----
            float S[8][4];
#pragma unroll
            for (int nt = 0; nt < 8; nt++)
#pragma unroll
                for (int c = 0; c < 4; c++) S[nt][c] = 0.0f;

#pragma unroll
            for (int np = 0; np < 4; np++) {
#pragma unroll
                for (int kc = 0; kc < 4; kc++) {
                    uint32_t rh[4], rl[4];
                    ldsm_x4(rh, st + FKH + (np * 16 + lrow) * FPITCH + kc * 32 + lkb);
                    ldsm_x4(rl, st + FKL + (np * 16 + lrow) * FPITCH + kc * 32 + lkb);
                    uint32_t bh0[2] = {rh[0], rh[2]}, bh1[2] = {rh[1], rh[3]};
                    uint32_t bl0[2] = {rl[0], rl[2]}, bl1[2] = {rl[1], rl[3]};
                    float* s0 = S[np * 2];
                    float* s1 = S[np * 2 + 1];
                    mma_bf16(s0, qfh[kc], bh0);
                    mma_bf16(s0, qfh[kc], bl0);
                    mma_bf16(s0, qfl[kc], bh0);
                    mma_bf16(s1, qfh[kc], bh1);
                    mma_bf16(s1, qfh[kc], bl1);
                    mma_bf16(s1, qfl[kc], bh1);
                }
            }

            // ---- causal mask (only when tile crosses the diagonal) ----
            if (j * 64 + 63 > q0 + wm) {
#pragma unroll
                for (int nt = 0; nt < 8; nt++) {
                    int c0 = j * 64 + nt * 8 + (lane & 3) * 2;
                    if (c0     > rA) S[nt][0] = -1e30f;
                    if (c0 + 1 > rA) S[nt][1] = -1e30f;
                    if (c0     > rB) S[nt][2] = -1e30f;
                    if (c0 + 1 > rB) S[nt][3] = -1e30f;
                }
            }

            // ---- online softmax ----
            float mxA = -1e30f, mxB = -1e30f;
#pragma unroll
            for (int nt = 0; nt < 8; nt++) {
                mxA = fmaxf(mxA, fmaxf(S[nt][0], S[nt][1]));
                mxB = fmaxf(mxB, fmaxf(S[nt][2], S[nt][3]));
            }
#pragma unroll
            for (int off = 1; off <= 2; off <<= 1) {
                mxA = fmaxf(mxA, __shfl_xor_sync(0xffffffffu, mxA, off));
                mxB = fmaxf(mxB, __shfl_xor_sync(0xffffffffu, mxB, off));
            }
            const float mnA = fmaxf(mA, mxA);
            const float mnB = fmaxf(mB, mxB);
            const float aA  = __expf(mA - mnA);
            const float aB  = __expf(mB - mnB);
            mA = mnA; mB = mnB;

            float sA = 0.0f, sB = 0.0f;
#pragma unroll
            for (int nt = 0; nt < 8; nt++) {
                S[nt][0] = __expf(S[nt][0] - mnA);
                S[nt][1] = __expf(S[nt][1] - mnA);
                S[nt][2] = __expf(S[nt][2] - mnB);
                S[nt][3] = __expf(S[nt][3] - mnB);
                sA += S[nt][0] + S[nt][1];
                sB += S[nt][2] + S[nt][3];
            }
#pragma unroll
            for (int off = 1; off <= 2; off <<= 1) {
                sA += __shfl_xor_sync(0xffffffffu, sA, off);
                sB += __shfl_xor_sync(0xffffffffu, sB, off);
            }
            lA = lA * aA + sA;
            lB = lB * aB + sB;
#pragma unroll
            for (int nt = 0; nt < 8; nt++) {
                O[nt][0] *= aA; O[nt][1] *= aA;
                O[nt][2] *= aB; O[nt][3] *= aB;
            }

            // ---- O += P V (bf16x3, P from registers) ----
#pragma unroll
            for (int kc = 0; kc < 4; kc++) {
                const float* p0 = S[kc * 2];
                const float* p1 = S[kc * 2 + 1];
                uint32_t ah[4], al[4];
                ah[0] = pack_hi(p0[0], p0[1]); al[0] = pack_lo(p0[0], p0[1]);
                ah[1] = pack_hi(p0[2], p0[3]); al[1] = pack_lo(p0[2], p0[3]);
                ah[2] = pack_hi(p1[0], p1[1]); al[2] = pack_lo(p1[0], p1[1]);
                ah[3] = pack_hi(p1[2], p1[3]); al[3] = pack_lo(p1[2], p1[3]);
#pragma unroll
                for (int np = 0; np < 4; np++) {
                    uint32_t vh4[4], vl4[4];
                    ldsm_x4_t(vh4, st + FVH + (kc * 16 + lrow) * FPITCH + np * 32 + lkb);
                    ldsm_x4_t(vl4, st + FVL + (kc * 16 + lrow) * FPITCH + np * 32 + lkb);
                    uint32_t bvh0[2] = {vh4[0], vh4[1]}, bvh1[2] = {vh4[2], vh4[3]};
                    uint32_t bvl0[2] = {vl4[0], vl4[1]}, bvl1[2] = {vl4[2], vl4[3]};
                    float* o0 = O[np * 2];
                    float* o1 = O[np * 2 + 1];
                    mma_bf16(o0, ah, bvh0);
                    mma_bf16(o0, ah, bvl0);
                    mma_bf16(o0, al, bvh0);
                    mma_bf16(o1, ah, bvh1);
                    mma_bf16(o1, ah, bvl1);
                    mma_bf16(o1, al, bvh1);
                }
            }
        }

        __syncthreads();
        if (j + 2 < nkv) load_kv(j & 1, j + 2);
    }

    // ---- epilogue: normalize, split to bf16 hi/lo att ----
    const float iA = 1.0f / lA;
    const float iB = 1.0f / lB;
#pragma unroll
    for (int nt = 0; nt < 8; nt++) {
        const int col = h * 64 + nt * 8 + (lane & 3) * 2;
        float v0 = O[nt][0] * iA, v1 = O[nt][1] * iA;
        float v2 = O[nt][2] * iB, v3 = O[nt][3] * iB;
        size_t oA = (size_t)(b * T_ + rA) * C_ + col;
        size_t oB = (size_t)(b * T_ + rB) * C_ + col;
        *(uint32_t*)(ohi + oA) = pack_hi(v0, v1);
        *(uint32_t*)(olo + oA) = pack_lo(v0, v1);
        *(uint32_t*)(ohi + oB) = pack_hi(v2, v3);
        *(uint32_t*)(olo + oB) = pack_lo(v2, v3);
    }
}

// ---------------------------------------------------------------------------
// Launcher
// ---------------------------------------------------------------------------
extern "C" void kernel_launch(void* const* d_in, const int* in_sizes, int n_in,
                              void* d_out, int out_size)
{
    (void)in_sizes; (void)n_in; (void)out_size;
    const float* x      = (const float*)d_in[0];
    const float* w_attn = (const float*)d_in[1];
    const float* b_attn = (const float*)d_in[2];
    const float* w_proj = (const float*)d_in[3];
    const float* b_proj = (const float*)d_in[4];
    float* out = (float*)d_out;

    void *xhi_p, *xlo_p, *wahi_p, *walo_p, *wphi_p, *wplo_p, *athi_p, *atlo_p;
    void *qh_p, *ql_p, *kh_p, *kl_p, *vh_p, *vl_p;
    cudaGetSymbolAddress(&xhi_p,  g_xhi);
    cudaGetSymbolAddress(&xlo_p,  g_xlo);
    cudaGetSymbolAddress(&wahi_p, g_wahi);
    cudaGetSymbolAddress(&walo_p, g_walo);
    cudaGetSymbolAddress(&wphi_p, g_wphi);
    cudaGetSymbolAddress(&wplo_p, g_wplo);
    cudaGetSymbolAddress(&athi_p, g_atthi);
    cudaGetSymbolAddress(&atlo_p, g_attlo);
    cudaGetSymbolAddress(&qh_p, g_qh);
    cudaGetSymbolAddress(&ql_p, g_ql);
    cudaGetSymbolAddress(&kh_p, g_kh);
    cudaGetSymbolAddress(&kl_p, g_kl);
    cudaGetSymbolAddress(&vh_p, g_vh);
    cudaGetSymbolAddress(&vl_p, g_vl);

    cudaFuncSetAttribute(gemm_bf16x3,
                         cudaFuncAttributeMaxDynamicSharedMemorySize, GEMM_SMEM);
    cudaFuncSetAttribute(flash_attn_tc,
                         cudaFuncAttributeMaxDynamicSharedMemorySize, FLASH_SMEM);

    // Prep
    {
        size_t n4 = (size_t)MTOT * C_ / 4;
        split_rows<<<(unsigned)(n4 / 256), 256>>>(
            x, (__nv_bfloat16*)xhi_p, (__nv_bfloat16*)xlo_p);

        dim3 ga(C3_ / 32, C_ / 32);
        transpose_split<<<ga, dim3(32, 8)>>>(
            w_attn, (__nv_bfloat16*)wahi_p, (__nv_bfloat16*)walo_p, C_, C3_);

        dim3 gp(C_ / 32, C_ / 32);
        transpose_split<<<gp, dim3(32, 8)>>>(
            w_proj, (__nv_bfloat16*)wphi_p, (__nv_bfloat16*)wplo_p, C_, C_);
    }

    // Stage 1: QKV gemm with split-store epilogue
    {
        dim3 grid(C3_ / 128, MTOT / 128);
        gemm_bf16x3<<<grid, 256, GEMM_SMEM>>>(
            (const __nv_bfloat16*)xhi_p, (const __nv_bfloat16*)xlo_p,
            (const __nv_bfloat16*)wahi_p, (const __nv_bfloat16*)walo_p,
            b_attn, nullptr, MTOT, C3_, C_, 1,
            (__nv_bfloat16*)qh_p, (__nv_bfloat16*)ql_p,
            (__nv_bfloat16*)kh_p, (__nv_bfloat16*)kl_p,
            (__nv_bfloat16*)vh_p, (__nv_bfloat16*)vl_p);
    }

    // Stage 2: tensor-core flash attention
    {
        dim3 grid(T_ / 128, H_, B_);
        flash_attn_tc<<<grid, 256, FLASH_SMEM>>>(
            (const __nv_bfloat16*)qh_p, (const __nv_bfloat16*)ql_p,
            (const __nv_bfloat16*)kh_p, (const __nv_bfloat16*)kl_p,
            (const __nv_bfloat16*)vh_p, (const __nv_bfloat16*)vl_p,
            (__nv_bfloat16*)athi_p, (__nv_bfloat16*)atlo_p);
    }

    // Stage 3: out = att @ w_proj + b_proj
    {
        dim3 grid(C_ / 128, MTOT / 128);
        gemm_bf16x3<<<grid, 256, GEMM_SMEM>>>(
            (const __nv_bfloat16*)athi_p, (const __nv_bfloat16*)atlo_p,
            (const __nv_bfloat16*)wphi_p, (const __nv_bfloat16*)wplo_p,
            b_proj, out, MTOT, C_, C_, 0,
            nullptr, nullptr, nullptr, nullptr, nullptr, nullptr);
    }
}

// round 6
// speedup vs baseline: 2.7105x; 1.0067x over previous
#include <cuda_runtime.h>
#include <cuda_bf16.h>
#include <cstdint>

// Problem constants
#define B_   4
#define T_   2048
#define C_   1024
#define H_   16
#define C3_  3072
#define MTOT (B_ * T_)   // 8192

// Scratch (__device__ globals; no allocations allowed)
__device__ __nv_bfloat16 g_xhi[(size_t)MTOT * C_];
__device__ __nv_bfloat16 g_xlo[(size_t)MTOT * C_];
__device__ __nv_bfloat16 g_wahi[(size_t)C3_ * C_];          // w_attn^T [N][K]
__device__ __nv_bfloat16 g_walo[(size_t)C3_ * C_];
__device__ __nv_bfloat16 g_wphi[(size_t)C_ * C_];           // w_proj^T [N][K]
__device__ __nv_bfloat16 g_wplo[(size_t)C_ * C_];
__device__ __nv_bfloat16 g_atthi[(size_t)MTOT * C_];
__device__ __nv_bfloat16 g_attlo[(size_t)MTOT * C_];
#define QKV_ELEMS ((size_t)B_ * H_ * T_ * 64)
__device__ __nv_bfloat16 g_qh[QKV_ELEMS];
__device__ __nv_bfloat16 g_ql[QKV_ELEMS];
__device__ __nv_bfloat16 g_kh[QKV_ELEMS];
__device__ __nv_bfloat16 g_kl[QKV_ELEMS];
__device__ __nv_bfloat16 g_vh[QKV_ELEMS];
__device__ __nv_bfloat16 g_vl[QKV_ELEMS];

// ===========================================================================
// sm_100-base PTX helpers
// ===========================================================================
__device__ __forceinline__ uint32_t smem_u32(const void* p) {
    uint32_t a;
    asm("{ .reg .u64 t; cvta.to.shared.u64 t, %1; cvt.u32.u64 %0, t; }"
        : "=r"(a) : "l"(p));
    return a;
}

__device__ __forceinline__ void cp16(uint32_t dst, const void* src) {
    asm volatile("cp.async.cg.shared.global [%0], [%1], 16;"
                 :: "r"(dst), "l"(src) : "memory");
}
#define CP_COMMIT() asm volatile("cp.async.commit_group;" ::: "memory")
#define CP_WAIT(n)  asm volatile("cp.async.wait_group %0;" :: "n"(n) : "memory")

__device__ __forceinline__ void ldsm_x4(uint32_t* r, uint32_t addr) {
    asm volatile("ldmatrix.sync.aligned.m8n8.x4.shared.b16 {%0,%1,%2,%3}, [%4];"
                 : "=r"(r[0]), "=r"(r[1]), "=r"(r[2]), "=r"(r[3]) : "r"(addr));
}
__device__ __forceinline__ void ldsm_x4_t(uint32_t* r, uint32_t addr) {
    asm volatile("ldmatrix.sync.aligned.m8n8.x4.trans.shared.b16 {%0,%1,%2,%3}, [%4];"
                 : "=r"(r[0]), "=r"(r[1]), "=r"(r[2]), "=r"(r[3]) : "r"(addr));
}

__device__ __forceinline__ void mma_bf16(float* c, const uint32_t* a,
                                         const uint32_t* b) {
    asm volatile(
        "mma.sync.aligned.m16n8k16.row.col.f32.bf16.bf16.f32 "
        "{%0,%1,%2,%3}, {%4,%5,%6,%7}, {%8,%9}, {%0,%1,%2,%3};"
        : "+f"(c[0]), "+f"(c[1]), "+f"(c[2]), "+f"(c[3])
        : "r"(a[0]), "r"(a[1]), "r"(a[2]), "r"(a[3]), "r"(b[0]), "r"(b[1]));
}

__device__ __forceinline__ uint32_t pack_bf16(__nv_bfloat16 a, __nv_bfloat16 b) {
    return (uint32_t)__bfloat16_as_ushort(a) |
           ((uint32_t)__bfloat16_as_ushort(b) << 16);
}
__device__ __forceinline__ uint32_t pack_hi(float x, float y) {
    return pack_bf16(__float2bfloat16(x), __float2bfloat16(y));
}
__device__ __forceinline__ uint32_t pack_lo(float x, float y) {
    __nv_bfloat16 hx = __float2bfloat16(x), hy = __float2bfloat16(y);
    return pack_bf16(__float2bfloat16(x - __bfloat162float(hx)),
                     __float2bfloat16(y - __bfloat162float(hy)));
}

// ===========================================================================
// Prep kernels
// ===========================================================================
__global__ __launch_bounds__(256) void split_rows(
    const float* __restrict__ in,
    __nv_bfloat16* __restrict__ hi, __nv_bfloat16* __restrict__ lo)
{
    size_t i = ((size_t)blockIdx.x * 256 + threadIdx.x) * 4;
    float4 v = *(const float4*)(in + i);
    uint2 ph = {pack_hi(v.x, v.y), pack_hi(v.z, v.w)};
    uint2 pl = {pack_lo(v.x, v.y), pack_lo(v.z, v.w)};
    *(uint2*)(hi + i) = ph;
    *(uint2*)(lo + i) = pl;
}

__global__ __launch_bounds__(256) void transpose_split(
    const float* __restrict__ in,
    __nv_bfloat16* __restrict__ hi, __nv_bfloat16* __restrict__ lo,
    int K, int N)
{
    __shared__ float t[32][33];
    const int n0 = blockIdx.x * 32;
    const int k0 = blockIdx.y * 32;
    const int tx = threadIdx.x;
    const int ty = threadIdx.y;
#pragma unroll
    for (int j = 0; j < 32; j += 8)
        t[ty + j][tx] = in[(size_t)(k0 + ty + j) * N + n0 + tx];
    __syncthreads();
#pragma unroll
    for (int j = 0; j < 32; j += 8) {
        float v = t[tx][ty + j];
        __nv_bfloat16 h = __float2bfloat16(v);
        __nv_bfloat16 l = __float2bfloat16(v - __bfloat162float(h));
        size_t o = (size_t)(n0 + ty + j) * K + k0 + tx;
        hi[o] = h;
        lo[o] = l;
    }
}

// ===========================================================================
// bf16x3 tensor-core GEMM. mode 0: fp32 out + bias. mode 1: split-store QKV.
// ===========================================================================
#define PITCH_B   80
#define TILE_B    (128 * PITCH_B)
#define STAGE_B   (4 * TILE_B)
#define GEMM_SMEM (2 * STAGE_B)

__global__ __launch_bounds__(256) void gemm_bf16x3(
    const __nv_bfloat16* __restrict__ Ahi, const __nv_bfloat16* __restrict__ Alo,
    const __nv_bfloat16* __restrict__ Bhi, const __nv_bfloat16* __restrict__ Blo,
    const float* __restrict__ bias, float* __restrict__ Cout,
    int M, int N, int K, int qkv_mode,
    __nv_bfloat16* qh, __nv_bfloat16* ql,
    __nv_bfloat16* kh, __nv_bfloat16* kl,
    __nv_bfloat16* vh, __nv_bfloat16* vl)
{
    extern __shared__ char smem[];
    const uint32_t sbase = smem_u32(smem);
    const int tid  = threadIdx.x;
    const int wid  = tid >> 5;
    const int lane = tid & 31;
    const int m0 = blockIdx.y * 128;
    const int n0 = blockIdx.x * 128;
    const int wm = (wid & 1) * 64;
    const int wn = (wid >> 1) * 32;

    const int nchunks = K >> 5;

    // ---- hoisted load-stage index math (fixed per thread) ----
    uint32_t soff[2];
    size_t   aoff[2], boff[2];
#pragma unroll
    for (int i = 0; i < 2; i++) {
        int idx = tid + i * 256;
        int row = idx >> 2;
        int ch  = idx & 3;
        soff[i] = (uint32_t)row * PITCH_B + ch * 16;
        aoff[i] = (size_t)(m0 + row) * K + ch * 8;
        boff[i] = (size_t)(n0 + row) * K + ch * 8;
    }

    auto load_stage = [&](int buf, int kc) {
        const int k0 = kc << 5;
        const uint32_t base = sbase + buf * STAGE_B;
#pragma unroll
        for (int i = 0; i < 2; i++) {
            cp16(base + soff[i],              Ahi + aoff[i] + k0);
            cp16(base + TILE_B + soff[i],     Alo + aoff[i] + k0);
            cp16(base + 2 * TILE_B + soff[i], Bhi + boff[i] + k0);
            cp16(base + 3 * TILE_B + soff[i], Blo + boff[i] + k0);
        }
    };

    float acc[4][4][4];
#pragma unroll
    for (int a = 0; a < 4; a++)
#pragma unroll
        for (int b = 0; b < 4; b++)
#pragma unroll
            for (int c = 0; c < 4; c++) acc[a][b][c] = 0.0f;

    load_stage(0, 0); CP_COMMIT();
    load_stage(1, 1); CP_COMMIT();

    const uint32_t lrow = lane & 15;
    const uint32_t lkb  = (lane >> 4) * 16;

    for (int c = 0; c < nchunks; c++) {
        if (c + 1 < nchunks) { CP_WAIT(1); } else { CP_WAIT(0); }
        __syncthreads();

        const uint32_t st   = sbase + (c & 1) * STAGE_B;
        const uint32_t sAhi = st;
        const uint32_t sAlo = st + TILE_B;
        const uint32_t sBhi = st + 2 * TILE_B;
        const uint32_t sBlo = st + 3 * TILE_B;

#pragma unroll
        for (int ks = 0; ks < 2; ks++) {
            const uint32_t kb = (uint32_t)(ks * 32) + lkb;

            uint32_t Bh[4][2], Bl[4][2];
            {
                uint32_t r[4];
                ldsm_x4(r, sBhi + (wn + lrow) * PITCH_B + kb);
                Bh[0][0] = r[0]; Bh[1][0] = r[1]; Bh[0][1] = r[2]; Bh[1][1] = r[3];
                ldsm_x4(r, sBhi + (wn + 16 + lrow) * PITCH_B + kb);
                Bh[2][0] = r[0]; Bh[3][0] = r[1]; Bh[2][1] = r[2]; Bh[3][1] = r[3];
                ldsm_x4(r, sBlo + (wn + lrow) * PITCH_B + kb);
                Bl[0][0] = r[0]; Bl[1][0] = r[1]; Bl[0][1] = r[2]; Bl[1][1] = r[3];
                ldsm_x4(r, sBlo + (wn + 16 + lrow) * PITCH_B + kb);
                Bl[2][0] = r[0]; Bl[3][0] = r[1]; Bl[2][1] = r[2]; Bl[3][1] = r[3];
            }

#pragma unroll
            for (int mt = 0; mt < 4; mt++) {
                uint32_t Ah[4], Al[4];
                ldsm_x4(Ah, sAhi + (wm + mt * 16 + lrow) * PITCH_B + kb);
                ldsm_x4(Al, sAlo + (wm + mt * 16 + lrow) * PITCH_B + kb);
                // 3 term-passes of 4 distinct accumulators each:
                // same-acc reuse distance = 4 MMAs (was 1).
#pragma unroll
                for (int nt = 0; nt < 4; nt++) mma_bf16(acc[mt][nt], Ah, Bh[nt]);
#pragma unroll
                for (int nt = 0; nt < 4; nt++) mma_bf16(acc[mt][nt], Ah, Bl[nt]);
#pragma unroll
                for (int nt = 0; nt < 4; nt++) mma_bf16(acc[mt][nt], Al, Bh[nt]);
            }
        }
        __syncthreads();

        if (c + 2 < nchunks) { load_stage(c & 1, c + 2); CP_COMMIT(); }
    }

    const int lr = lane >> 2;
    const int lc = (lane & 3) * 2;

    if (!qkv_mode) {
#pragma unroll
        for (int nt = 0; nt < 4; nt++) {
            const int col = n0 + wn + nt * 8 + lc;
            float2 bv = *(const float2*)(bias + col);
#pragma unroll
            for (int mt = 0; mt < 4; mt++) {
                const int mrow = m0 + wm + mt * 16 + lr;
                float2 o0 = {acc[mt][nt][0] + bv.x, acc[mt][nt][1] + bv.y};
                float2 o1 = {acc[mt][nt][2] + bv.x, acc[mt][nt][3] + bv.y};
                *(float2*)(Cout + (size_t)mrow * N + col) = o0;
                *(float2*)(Cout + (size_t)(mrow + 8) * N + col) = o1;
            }
        }
    } else {
#pragma unroll
        for (int nt = 0; nt < 4; nt++) {
            const int col = n0 + wn + nt * 8 + lc;
            float2 bv = *(const float2*)(bias + col);
            const int sec = col >> 10;
            const int r   = col & 1023;
            const int hh  = r >> 6;
            const int dd  = r & 63;
            __nv_bfloat16* dh = (sec == 0) ? qh : (sec == 1) ? kh : vh;
            __nv_bfloat16* dl = (sec == 0) ? ql : (sec == 1) ? kl : vl;
            const float sc = (sec == 0) ? 0.125f : 1.0f;
#pragma unroll
            for (int mt = 0; mt < 4; mt++) {
                const int mrow = m0 + wm + mt * 16 + lr;
                const int bb = mrow >> 11;
                const int tt = mrow & 2047;
                size_t off = ((size_t)(bb * H_ + hh) * T_ + tt) * 64 + dd;
                float v0 = (acc[mt][nt][0] + bv.x) * sc;
                float v1 = (acc[mt][nt][1] + bv.y) * sc;
                float v2 = (acc[mt][nt][2] + bv.x) * sc;
                float v3 = (acc[mt][nt][3] + bv.y) * sc;
                *(uint32_t*)(dh + off)       = pack_hi(v0, v1);
                *(uint32_t*)(dl + off)       = pack_lo(v0, v1);
                *(uint32_t*)(dh + off + 512) = pack_hi(v2, v3);
                *(uint32_t*)(dl + off + 512) = pack_lo(v2, v3);
            }
        }
    }
}

// ===========================================================================
// Tensor-core causal flash attention (bf16x3, register P).
// ===========================================================================
#define FPITCH     144
#define FSTAGE     36864
#define FKH        0
#define FKL        9216
#define FVH        18432
#define FVL        27648
#define FLASH_SMEM (2 * FSTAGE)

__global__ __launch_bounds__(256) void flash_attn_tc(
    const __nv_bfloat16* __restrict__ Qh, const __nv_bfloat16* __restrict__ Ql,
    const __nv_bfloat16* __restrict__ Kh, const __nv_bfloat16* __restrict__ Kl,
    const __nv_bfloat16* __restrict__ Vh, const __nv_bfloat16* __restrict__ Vl,
    __nv_bfloat16* __restrict__ ohi, __nv_bfloat16* __restrict__ olo)
{
    const int qt = blockIdx.x;
    const int h  = blockIdx.y;
    const int b  = blockIdx.z;
    const int q0 = qt * 128;
    const size_t gbase = (size_t)(b * H_ + h) * T_ * 64;

    extern __shared__ char smem[];
    const uint32_t sbase = smem_u32(smem);
    const int tid  = threadIdx.x;
    const int wid  = tid >> 5;
    const int lane = tid & 31;
    const uint32_t lrow = lane & 15;
    const uint32_t lkb  = (lane >> 4) * 16;
    const int wm = wid * 16;

    // ---- load Q tile, extract fragments ----
#pragma unroll
    for (int i = 0; i < 8; i++) {
        int idx = tid + i * 256;
        int mat = idx >> 10;
        int rem = idx & 1023;
        int row = rem >> 3;
        int ch  = rem & 7;
        const __nv_bfloat16* src = (mat ? Ql : Qh) + gbase +
                                   (size_t)(q0 + row) * 64 + ch * 8;
        cp16(sbase + mat * 18432 + row * FPITCH + ch * 16, src);
    }
    CP_COMMIT(); CP_WAIT(0);
    __syncthreads();

    uint32_t qfh[4][4], qfl[4][4];
#pragma unroll
    for (int kc = 0; kc < 4; kc++) {
        ldsm_x4(qfh[kc], sbase +         (wm + lrow) * FPITCH + kc * 32 + lkb);
        ldsm_x4(qfl[kc], sbase + 18432 + (wm + lrow) * FPITCH + kc * 32 + lkb);
    }
    __syncthreads();

    auto load_kv = [&](int buf, int j) {
        const int kv0 = j * 64;
        const uint32_t st = sbase + buf * FSTAGE;
#pragma unroll
        for (int i = 0; i < 8; i++) {
            int idx = tid + i * 256;
            int mat = idx >> 9;
            int rem = idx & 511;
            int row = rem >> 3;
            int ch  = rem & 7;
            const __nv_bfloat16* src =
                (mat == 0 ? Kh : mat == 1 ? Kl : mat == 2 ? Vh : Vl) +
                gbase + (size_t)(kv0 + row) * 64 + ch * 8;
            cp16(st + mat * 9216 + row * FPITCH + ch * 16, src);
        }
        CP_COMMIT();
    };

    const int nkv = 2 * qt + 2;
    load_kv(0, 0);
    load_kv(1, 1);

    const int rA = q0 + wm + (lane >> 2);
    const int rB = rA + 8;

    float mA = -1e30f, mB = -1e30f, lA = 0.0f, lB = 0.0f;
    float O[8][4];
#pragma unroll
    for (int nt = 0; nt < 8; nt++)
#pragma unroll
        for (int c = 0; c < 4; c++) O[nt][c] = 0.0f;

    for (int j = 0; j < nkv; j++) {
        if (j + 1 < nkv) { CP_WAIT(1); } else { CP_WAIT(0); }
        __syncthreads();

        const uint32_t st = sbase + (j & 1) * FSTAGE;
        const bool skip = (j * 64 > q0 + wm + 15);

        if (!skip) {
            // ---- S = Q K^T (bf16x3), kc-outer, 2-np blocking ----
            float S[8][4];
#pragma unroll
            for (int nt = 0; nt < 8; nt++)
#pragma unroll
                for (int c = 0; c < 4; c++) S[nt][c] = 0.0f;

#pragma unroll
            for (int kc = 0; kc < 4; kc++) {
#pragma unroll
                for (int nb = 0; nb < 2; nb++) {
                    const int np0 = nb * 2, np1 = nb * 2 + 1;
                    uint32_t rh0[4], rl0[4], rh1[4], rl1[4];
                    ldsm_x4(rh0, st + FKH + (np0 * 16 + lrow) * FPITCH + kc * 32 + lkb);
                    ldsm_x4(rh1, st + FKH + (np1 * 16 + lrow) * FPITCH + kc * 32 + lkb);
                    ldsm_x4(rl0, st + FKL + (np0 * 16 + lrow) * FPITCH + kc * 32 + lkb);
                    ldsm_x4(rl1, st + FKL + (np1 * 16 + lrow) * FPITCH + kc * 32 + lkb);
                    uint32_t bh00[2] = {rh0[0], rh0[2]}, bh01[2] = {rh0[1], rh0[3]};
                    uint32_t bh10[2] = {rh1[0], rh1[2]}, bh11[2] = {rh1[1], rh1[3]};
                    uint32_t bl00[2] = {rl0[0], rl0[2]}, bl01[2] = {rl0[1], rl0[3]};
                    uint32_t bl10[2] = {rl1[0], rl1[2]}, bl11[2] = {rl1[1], rl1[3]};
                    // term passes: same-acc reuse distance 4
                    mma_bf16(S[np0 * 2],     qfh[kc], bh00);
                    mma_bf16(S[np0 * 2 + 1], qfh[kc], bh01);
                    mma_bf16(S[np1 * 2],     qfh[kc], bh10);
                    mma_bf16(S[np1 * 2 + 1], qfh[kc], bh11);
                    mma_bf16(S[np0 * 2],     qfh[kc], bl00);
                    mma_bf16(S[np0 * 2 + 1], qfh[kc], bl01);
                    mma_bf16(S[np1 * 2],     qfh[kc], bl10);
                    mma_bf16(S[np1 * 2 + 1], qfh[kc], bl11);
                    mma_bf16(S[np0 * 2],     qfl[kc], bh00);
                    mma_bf16(S[np0 * 2 + 1], qfl[kc], bh01);
                    mma_bf16(S[np1 * 2],     qfl[kc], bh10);
                    mma_bf16(S[np1 * 2 + 1], qfl[kc], bh11);
                }
            }

            // ---- causal mask ----
            if (j * 64 + 63 > q0 + wm) {
#pragma unroll
                for (int nt = 0; nt < 8; nt++) {
                    int c0 = j * 64 + nt * 8 + (lane & 3) * 2;
                    if (c0     > rA) S[nt][0] = -1e30f;
                    if (c0 + 1 > rA) S[nt][1] = -1e30f;
                    if (c0     > rB) S[nt][2] = -1e30f;
                    if (c0 + 1 > rB) S[nt][3] = -1e30f;
                }
            }

            // ---- online softmax ----
            float mxA = -1e30f, mxB = -1e30f;
#pragma unroll
            for (int nt = 0; nt < 8; nt++) {
                mxA = fmaxf(mxA, fmaxf(S[nt][0], S[nt][1]));
                mxB = fmaxf(mxB, fmaxf(S[nt][2], S[nt][3]));
            }
#pragma unroll
            for (int off = 1; off <= 2; off <<= 1) {
                mxA = fmaxf(mxA, __shfl_xor_sync(0xffffffffu, mxA, off));
                mxB = fmaxf(mxB, __shfl_xor_sync(0xffffffffu, mxB, off));
            }
            const float mnA = fmaxf(mA, mxA);
            const float mnB = fmaxf(mB, mxB);
            const float aA  = __expf(mA - mnA);
            const float aB  = __expf(mB - mnB);
            mA = mnA; mB = mnB;

            float sA = 0.0f, sB = 0.0f;
#pragma unroll
            for (int nt = 0; nt < 8; nt++) {
                S[nt][0] = __expf(S[nt][0] - mnA);
                S[nt][1] = __expf(S[nt][1] - mnA);
                S[nt][2] = __expf(S[nt][2] - mnB);
                S[nt][3] = __expf(S[nt][3] - mnB);
                sA += S[nt][0] + S[nt][1];
                sB += S[nt][2] + S[nt][3];
            }
#pragma unroll
            for (int off = 1; off <= 2; off <<= 1) {
                sA += __shfl_xor_sync(0xffffffffu, sA, off);
                sB += __shfl_xor_sync(0xffffffffu, sB, off);
            }
            lA = lA * aA + sA;
            lB = lB * aB + sB;
#pragma unroll
            for (int nt = 0; nt < 8; nt++) {
                O[nt][0] *= aA; O[nt][1] *= aA;
                O[nt][2] *= aB; O[nt][3] *= aB;
            }

            // ---- O += P V (bf16x3), 2-np blocking ----
#pragma unroll
            for (int kc = 0; kc < 4; kc++) {
                const float* p0 = S[kc * 2];
                const float* p1 = S[kc * 2 + 1];
                uint32_t ah[4], al[4];
                ah[0] = pack_hi(p0[0], p0[1]); al[0] = pack_lo(p0[0], p0[1]);
                ah[1] = pack_hi(p0[2], p0[3]); al[1] = pack_lo(p0[2], p0[3]);
                ah[2] = pack_hi(p1[0], p1[1]); al[2] = pack_lo(p1[0], p1[1]);
                ah[3] = pack_hi(p1[2], p1[3]); al[3] = pack_lo(p1[2], p1[3]);
#pragma unroll
                for (int nb = 0; nb < 2; nb++) {
                    const int np0 = nb * 2, np1 = nb * 2 + 1;
                    uint32_t vh0[4], vl0[4], vh1[4], vl1[4];
                    ldsm_x4_t(vh0, st + FVH + (kc * 16 + lrow) * FPITCH + np0 * 32 + lkb);
                    ldsm_x4_t(vh1, st + FVH + (kc * 16 + lrow) * FPITCH + np1 * 32 + lkb);
                    ldsm_x4_t(vl0, st + FVL + (kc * 16 + lrow) * FPITCH + np0 * 32 + lkb);
                    ldsm_x4_t(vl1, st + FVL + (kc * 16 + lrow) * FPITCH + np1 * 32 + lkb);
                    uint32_t bvh00[2] = {vh0[0], vh0[1]}, bvh01[2] = {vh0[2], vh0[3]};
                    uint32_t bvh10[2] = {vh1[0], vh1[1]}, bvh11[2] = {vh1[2], vh1[3]};
                    uint32_t bvl00[2] = {vl0[0], vl0[1]}, bvl01[2] = {vl0[2], vl0[3]};
                    uint32_t bvl10[2] = {vl1[0], vl1[1]}, bvl11[2] = {vl1[2], vl1[3]};
                    mma_bf16(O[np0 * 2],     ah, bvh00);
                    mma_bf16(O[np0 * 2 + 1], ah, bvh01);
                    mma_bf16(O[np1 * 2],     ah, bvh10);
                    mma_bf16(O[np1 * 2 + 1], ah, bvh11);
                    mma_bf16(O[np0 * 2],     ah, bvl00);
                    mma_bf16(O[np0 * 2 + 1], ah, bvl01);
                    mma_bf16(O[np1 * 2],     ah, bvl10);
                    mma_bf16(O[np1 * 2 + 1], ah, bvl11);
                    mma_bf16(O[np0 * 2],     al, bvh00);
                    mma_bf16(O[np0 * 2 + 1], al, bvh01);
                    mma_bf16(O[np1 * 2],     al, bvh10);
                    mma_bf16(O[np1 * 2 + 1], al, bvh11);
                }
            }
        }

        __syncthreads();
        if (j + 2 < nkv) load_kv(j & 1, j + 2);
    }

    // ---- epilogue ----
    const float iA = 1.0f / lA;
    const float iB = 1.0f / lB;
#pragma unroll
    for (int nt = 0; nt < 8; nt++) {
        const int col = h * 64 + nt * 8 + (lane & 3) * 2;
        float v0 = O[nt][0] * iA, v1 = O[nt][1] * iA;
        float v2 = O[nt][2] * iB, v3 = O[nt][3] * iB;
        size_t oA = (size_t)(b * T_ + rA) * C_ + col;
        size_t oB = (size_t)(b * T_ + rB) * C_ + col;
        *(uint32_t*)(ohi + oA) = pack_hi(v0, v1);
        *(uint32_t*)(olo + oA) = pack_lo(v0, v1);
        *(uint32_t*)(ohi + oB) = pack_hi(v2, v3);
        *(uint32_t*)(olo + oB) = pack_lo(v2, v3);
    }
}

// ---------------------------------------------------------------------------
// Launcher
// ---------------------------------------------------------------------------
extern "C" void kernel_launch(void* const* d_in, const int* in_sizes, int n_in,
                              void* d_out, int out_size)
{
    (void)in_sizes; (void)n_in; (void)out_size;
    const float* x      = (const float*)d_in[0];
    const float* w_attn = (const float*)d_in[1];
    const float* b_attn = (const float*)d_in[2];
    const float* w_proj = (const float*)d_in[3];
    const float* b_proj = (const float*)d_in[4];
    float* out = (float*)d_out;

    void *xhi_p, *xlo_p, *wahi_p, *walo_p, *wphi_p, *wplo_p, *athi_p, *atlo_p;
    void *qh_p, *ql_p, *kh_p, *kl_p, *vh_p, *vl_p;
    cudaGetSymbolAddress(&xhi_p,  g_xhi);
    cudaGetSymbolAddress(&xlo_p,  g_xlo);
    cudaGetSymbolAddress(&wahi_p, g_wahi);
    cudaGetSymbolAddress(&walo_p, g_walo);
    cudaGetSymbolAddress(&wphi_p, g_wphi);
    cudaGetSymbolAddress(&wplo_p, g_wplo);
    cudaGetSymbolAddress(&athi_p, g_atthi);
    cudaGetSymbolAddress(&atlo_p, g_attlo);
    cudaGetSymbolAddress(&qh_p, g_qh);
    cudaGetSymbolAddress(&ql_p, g_ql);
    cudaGetSymbolAddress(&kh_p, g_kh);
    cudaGetSymbolAddress(&kl_p, g_kl);
    cudaGetSymbolAddress(&vh_p, g_vh);
    cudaGetSymbolAddress(&vl_p, g_vl);

    cudaFuncSetAttribute(gemm_bf16x3,
                         cudaFuncAttributeMaxDynamicSharedMemorySize, GEMM_SMEM);
    cudaFuncSetAttribute(flash_attn_tc,
                         cudaFuncAttributeMaxDynamicSharedMemorySize, FLASH_SMEM);

    // Prep
    {
        size_t n4 = (size_t)MTOT * C_ / 4;
        split_rows<<<(unsigned)(n4 / 256), 256>>>(
            x, (__nv_bfloat16*)xhi_p, (__nv_bfloat16*)xlo_p);

        dim3 ga(C3_ / 32, C_ / 32);
        transpose_split<<<ga, dim3(32, 8)>>>(
            w_attn, (__nv_bfloat16*)wahi_p, (__nv_bfloat16*)walo_p, C_, C3_);

        dim3 gp(C_ / 32, C_ / 32);
        transpose_split<<<gp, dim3(32, 8)>>>(
            w_proj, (__nv_bfloat16*)wphi_p, (__nv_bfloat16*)wplo_p, C_, C_);
    }

    // Stage 1: QKV gemm with split-store epilogue
    {
        dim3 grid(C3_ / 128, MTOT / 128);
        gemm_bf16x3<<<grid, 256, GEMM_SMEM>>>(
            (const __nv_bfloat16*)xhi_p, (const __nv_bfloat16*)xlo_p,
            (const __nv_bfloat16*)wahi_p, (const __nv_bfloat16*)walo_p,
            b_attn, nullptr, MTOT, C3_, C_, 1,
            (__nv_bfloat16*)qh_p, (__nv_bfloat16*)ql_p,
            (__nv_bfloat16*)kh_p, (__nv_bfloat16*)kl_p,
            (__nv_bfloat16*)vh_p, (__nv_bfloat16*)vl_p);
    }

    // Stage 2: tensor-core flash attention
    {
        dim3 grid(T_ / 128, H_, B_);
        flash_attn_tc<<<grid, 256, FLASH_SMEM>>>(
            (const __nv_bfloat16*)qh_p, (const __nv_bfloat16*)ql_p,
            (const __nv_bfloat16*)kh_p, (const __nv_bfloat16*)kl_p,
            (const __nv_bfloat16*)vh_p, (const __nv_bfloat16*)vl_p,
            (__nv_bfloat16*)athi_p, (__nv_bfloat16*)atlo_p);
    }

    // Stage 3: out = att @ w_proj + b_proj
    {
        dim3 grid(C_ / 128, MTOT / 128);
        gemm_bf16x3<<<grid, 256, GEMM_SMEM>>>(
            (const __nv_bfloat16*)athi_p, (const __nv_bfloat16*)atlo_p,
            (const __nv_bfloat16*)wphi_p, (const __nv_bfloat16*)wplo_p,
            b_proj, out, MTOT, C_, C_, 0,
            nullptr, nullptr, nullptr, nullptr, nullptr, nullptr);
    }
}